// round 10
// baseline (speedup 1.0000x reference)
#include <cuda_runtime.h>

// GeneratorCell: B=128, M=32 queue rows, N=64 strokes, K=2048 stroke length
// Two kernels overlapped via PDL:
//   coef_kernel: conv -> GRU -> matvec -> g_coef2 (+ ht output)
//   fir_kernel:  stage emb+q (overlaps coef_kernel), sync, FIR, st/qt outputs
#define Bn 128
#define Mn 32
#define Nn 64
#define Kn 2048
#define NT 192                     // 6 warps per CTA (both kernels)
#define Cn 11                      // 192*11 = 2112 = N + M*N
#define PAD 72                     // bottom zero pad (even, >=66 for prefetch reach)
#define EMB_SZ (PAD + Kn + 64)     // ull elements

typedef unsigned long long ull;

__device__ ull g_coef2[Bn * Nn];   // (coef, coef) f32x2 per (batch, stroke) — 64KB

__device__ __forceinline__ float sigmoidf_(float x) { return 1.0f / (1.0f + __expf(-x)); }

__device__ __forceinline__ ull pack2(float x, float y) {
    ull r; asm("mov.b64 %0, {%1,%2};" : "=l"(r) : "f"(x), "f"(y)); return r;
}
__device__ __forceinline__ void unpack2(ull v, float& x, float& y) {
    asm("mov.b64 {%0,%1}, %2;" : "=f"(x), "=f"(y) : "l"(v));
}
__device__ __forceinline__ ull ffma2(ull a, ull b, ull c) {   // packed f32x2 FMA (sm_100+)
    ull d; asm("fma.rn.f32x2 %0, %1, %2, %3;" : "=l"(d) : "l"(a), "l"(b), "l"(c)); return d;
}

// ================= kernel A: coefficient chain (serial part) =================
__global__ __launch_bounds__(NT) void coef_kernel(
    const float* __restrict__ qt1, const float* __restrict__ ht1,
    const float* __restrict__ zt,  const float* __restrict__ alpha_t,
    const float* __restrict__ conv_w, const float* __restrict__ conv_b,
    const float* __restrict__ W_xr, const float* __restrict__ W_hr, const float* __restrict__ b_r,
    const float* __restrict__ W_xu, const float* __restrict__ W_hu, const float* __restrict__ b_u,
    const float* __restrict__ W_xn, const float* __restrict__ W_hn, const float* __restrict__ b_n,
    const float* __restrict__ lin_w, const float* __restrict__ lin_b,
    float* __restrict__ out)
{
    __shared__ float2 s_part[3 * Nn];
    __shared__ __align__(16) float s_ht[2 * Nn];

    const int b    = blockIdx.x;
    const int tid  = threadIdx.x;
    const int lane = tid & 31;
    const int wrp  = tid >> 5;
    const float2* qf = (const float2*)(qt1 + (size_t)b * Mn * Nn * 2);

    // ---- conv partials: 3 tap-groups x 11 taps (tap 32 = ht1 row) ----
    {
        const int n = tid & 63;
        const int g = tid >> 6;
        float2 v[11];
        #pragma unroll
        for (int k = 0; k < 11; k++) {
            const int h = g * 11 + k;
            v[k] = (h < 32) ? qf[h * Nn + n] : ((const float2*)ht1)[b * Nn + n];
        }
        float p0a = 0.f, p0b = 0.f, p1a = 0.f, p1b = 0.f;
        #pragma unroll
        for (int k = 0; k < 11; k++) {
            const int h = g * 11 + k;
            const float wa = conv_w[h],      wb = conv_w[33 + h];
            const float wc = conv_w[66 + h], wd = conv_w[99 + h];
            if (k & 1) {
                p0b = fmaf(v[k].x, wa, fmaf(v[k].y, wb, p0b));
                p1b = fmaf(v[k].x, wc, fmaf(v[k].y, wd, p1b));
            } else {
                p0a = fmaf(v[k].x, wa, fmaf(v[k].y, wb, p0a));
                p1a = fmaf(v[k].x, wc, fmaf(v[k].y, wd, p1a));
            }
        }
        s_part[g * Nn + n] = make_float2(p0a + p0b, p1a + p1b);
    }
    __syncthreads();

    // ---- preload lin_w row slices (hides under GRU) ----
    float4 lv[11];
    {
        const float4* lw4 = (const float4*)lin_w;             // [64 rows][32 float4]
        #pragma unroll
        for (int k = 0; k < 11; k++) {
            const int row = wrp * 11 + k;
            lv[k] = (row < Nn) ? lw4[row * 32 + lane] : make_float4(0.f, 0.f, 0.f, 0.f);
        }
    }

    // ---- GRU per stroke (tid<64) ----
    if (tid < 64) {
        const int n = tid;
        const float2 hv = ((const float2*)ht1)[b * Nn + n];   // L1 hit
        const float2 pa = s_part[n], pb = s_part[Nn + n], pc = s_part[2 * Nn + n];
        const float h0 = (pa.x + pb.x) + pc.x + conv_b[0];    // ht1 tap already in pc
        const float h1 = (pa.y + pb.y) + pc.y + conv_b[1];

        const float x0 = zt[b * Nn + n];
        const float x1 = alpha_t[b * Nn + n];

        float r0 = sigmoidf_(fmaf(x0, W_xr[0], fmaf(x1, W_xr[2], fmaf(h0, W_hr[0], fmaf(h1, W_hr[2], b_r[0])))));
        float r1 = sigmoidf_(fmaf(x0, W_xr[1], fmaf(x1, W_xr[3], fmaf(h0, W_hr[1], fmaf(h1, W_hr[3], b_r[1])))));
        float u0 = sigmoidf_(fmaf(x0, W_xu[0], fmaf(x1, W_xu[2], fmaf(h0, W_hu[0], fmaf(h1, W_hu[2], b_u[0])))));
        float u1 = sigmoidf_(fmaf(x0, W_xu[1], fmaf(x1, W_xu[3], fmaf(h0, W_hu[1], fmaf(h1, W_hu[3], b_u[1])))));

        const float rh0 = r0 * h0, rh1 = r1 * h1;
        float nt0 = tanhf(fmaf(x0, W_xn[0], fmaf(x1, W_xn[2], fmaf(rh0, W_hn[0], fmaf(rh1, W_hn[2], b_n[0])))));
        float nt1 = tanhf(fmaf(x0, W_xn[1], fmaf(x1, W_xn[3], fmaf(rh0, W_hn[1], fmaf(rh1, W_hn[3], b_n[1])))));

        const float hn0 = u0 * hv.x + (1.0f - u0) * nt0;
        const float hn1 = u1 * hv.y + (1.0f - u1) * nt1;

        s_ht[2 * n + 0] = hn0;
        s_ht[2 * n + 1] = hn1;

        const size_t off_ht = (size_t)Bn * Nn * 2 + (size_t)Bn * Mn * Nn * 2;
        ((float2*)(out + off_ht))[(size_t)b * Nn + n] = make_float2(hn0, hn1);
    }
    __syncthreads();

    // ---- matvec: coef[row] = (ht . lin_w[row] + lin_b[row]) * alpha[row] -> global ----
    {
        const float4 ht4 = ((const float4*)s_ht)[lane];
        #pragma unroll
        for (int k = 0; k < 11; k++) {
            const int row = wrp * 11 + k;
            if (row < Nn) {
                const float4 l = lv[k];
                float d = fmaf(l.x, ht4.x, fmaf(l.y, ht4.y, fmaf(l.z, ht4.z, l.w * ht4.w)));
                d += __shfl_xor_sync(0xffffffffu, d, 16);
                d += __shfl_xor_sync(0xffffffffu, d, 8);
                d += __shfl_xor_sync(0xffffffffu, d, 4);
                d += __shfl_xor_sync(0xffffffffu, d, 2);
                d += __shfl_xor_sync(0xffffffffu, d, 1);
                if (lane == 0) {
                    const float c = (d + lin_b[row]) * alpha_t[b * Nn + row];
                    g_coef2[b * Nn + row] = pack2(c, c);
                }
            }
        }
    }
}

// ================= kernel B: staging (overlaps A) + FIR + outputs =================
__global__ __launch_bounds__(NT) void fir_kernel(
    const float* __restrict__ qt1,
    const float* __restrict__ W_emb,
    float* __restrict__ out)
{
    __shared__ __align__(16) ull    s_exy[EMB_SZ];   // interleaved (x,y) emb, zero-padded
    __shared__ __align__(16) float2 s_q[Mn * Nn];    // q tile for output assembly
    __shared__ ull s_coef2[Nn];

    const int b   = blockIdx.x;
    const int tid = threadIdx.x;

    // ---- preamble: stage emb + q (independent of kernel A; overlaps it) ----
    {
        const float4* we4 = (const float4*)W_emb;    // 1024 float4
        const float4* qf4 = (const float4*)(qt1 + (size_t)b * Mn * Nn * 2);  // 1024 float4
        float4 e[6], qv[6];
        #pragma unroll
        for (int k = 0; k < 5; k++) { e[k] = we4[tid + k * NT]; qv[k] = qf4[tid + k * NT]; }
        if (tid < 64) { e[5] = we4[tid + 5 * NT]; qv[5] = qf4[tid + 5 * NT]; }

        if (tid < PAD) s_exy[tid] = 0ULL;
        if (tid >= 64 && tid < 128) s_exy[PAD + Kn + (tid - 64)] = 0ULL;

        float4* exy4 = (float4*)(s_exy + PAD);
        float4* sq4  = (float4*)s_q;
        #pragma unroll
        for (int k = 0; k < 5; k++) { exy4[tid + k * NT] = e[k]; sq4[tid + k * NT] = qv[k]; }
        if (tid < 64) { exy4[tid + 5 * NT] = e[5]; sq4[tid + 5 * NT] = qv[5]; }
    }

    // ---- wait for coef_kernel completion (PDL sync point) ----
    cudaGridDependencySynchronize();

    if (tid < Nn) s_coef2[tid] = g_coef2[b * Nn + tid];   // one coalesced 512B read
    __syncthreads();

    // ---- FIR overlap-add: C=11 sliding window, 1 LDS.64/iter + depth-1 prefetch ----
    const int p0 = tid * Cn;
    ull acc[Cn], w[Cn];
    #pragma unroll
    for (int i = 0; i < Cn; i++) {
        w[i] = s_exy[PAD + p0 + i];
        acc[i] = 0ULL;
    }
    ull nxt = s_exy[PAD + p0 - 1];
    #pragma unroll
    for (int n = 0; n < Nn; n++) {
        const ull c2 = s_coef2[n];                 // warp-uniform broadcast
        #pragma unroll
        for (int i = 0; i < Cn; i++) acc[i] = ffma2(c2, w[i], acc[i]);
        #pragma unroll
        for (int i = Cn - 1; i > 0; i--) w[i] = w[i - 1];   // renamed (full unroll)
        w[0] = nxt;
        nxt = s_exy[PAD + p0 - n - 2];             // min idx = PAD-65 = 7 >= 0
    }

    // ---- output assembly (q from shared) ----
    float2* st_out = (float2*)out + (size_t)b * Nn;
    float2* qt_out = (float2*)(out + (size_t)Bn * Nn * 2) + (size_t)b * Mn * Nn;
    #pragma unroll
    for (int i = 0; i < Cn; i++) {
        const int p = p0 + i;
        float fx, fy; unpack2(acc[i], fx, fy);
        float2 qv = make_float2(0.0f, 0.0f);
        if (p < Mn * Nn) qv = s_q[p];              // q_shift[j] = q_flat[j+N] = q_flat[p]
        float2 r = make_float2(qv.x + fx, qv.y + fy);
        if (p < Nn) st_out[p] = r;                 // st = q_row0 + f[:N]
        else        qt_out[p - Nn] = r;            // qt = q_shift + tail
    }
}

extern "C" void kernel_launch(void* const* d_in, const int* in_sizes, int n_in,
                              void* d_out, int out_size) {
    const float* qt1     = (const float*)d_in[0];
    const float* ht1     = (const float*)d_in[1];
    const float* zt      = (const float*)d_in[2];
    const float* alpha_t = (const float*)d_in[3];
    const float* conv_w  = (const float*)d_in[4];
    const float* conv_b  = (const float*)d_in[5];
    const float* W_xr    = (const float*)d_in[6];
    const float* W_hr    = (const float*)d_in[7];
    const float* b_r     = (const float*)d_in[8];
    const float* W_xu    = (const float*)d_in[9];
    const float* W_hu    = (const float*)d_in[10];
    const float* b_u     = (const float*)d_in[11];
    const float* W_xn    = (const float*)d_in[12];
    const float* W_hn    = (const float*)d_in[13];
    const float* b_n     = (const float*)d_in[14];
    const float* lin_w   = (const float*)d_in[15];
    const float* lin_b   = (const float*)d_in[16];
    const float* W_emb   = (const float*)d_in[17];
    float* out = (float*)d_out;

    // kernel A: coefficient chain
    coef_kernel<<<Bn, NT>>>(qt1, ht1, zt, alpha_t, conv_w, conv_b,
                            W_xr, W_hr, b_r, W_xu, W_hu, b_u,
                            W_xn, W_hn, b_n, lin_w, lin_b, out);

    // kernel B: launched with programmatic stream serialization (PDL) —
    // its preamble (emb + q staging) overlaps kernel A; it blocks at
    // cudaGridDependencySynchronize() until A completes.
    cudaLaunchConfig_t cfg = {};
    cfg.gridDim  = dim3(Bn);
    cfg.blockDim = dim3(NT);
    cfg.dynamicSmemBytes = 0;
    cfg.stream = 0;
    cudaLaunchAttribute attrs[1];
    attrs[0].id = cudaLaunchAttributeProgrammaticStreamSerialization;
    attrs[0].val.programmaticStreamSerializationAllowed = 1;
    cfg.attrs = attrs;
    cfg.numAttrs = 1;
    cudaLaunchKernelEx(&cfg, fir_kernel, qt1, W_emb, out);
}

// round 11
// speedup vs baseline: 1.1875x; 1.1875x over previous
#include <cuda_runtime.h>

// GeneratorCell: B=128, M=32 queue rows, N=64 strokes, K=2048 stroke length
#define Bn 128
#define Mn 32
#define Nn 64
#define Kn 2048
#define NT 192                     // 6 warps, 1 CTA per batch, grid=128
#define Cn 11                      // consecutive p's per thread; 192*11 = 2112 = N + M*N
#define PAD 72                     // bottom zero pad (even, >=66: loop reads down to p0-66)
#define EMB_SZ (PAD + Kn + 64)     // ull elements

typedef unsigned long long ull;

__device__ __forceinline__ float sigmoidf_(float x) { return 1.0f / (1.0f + __expf(-x)); }

__device__ __forceinline__ ull pack2(float x, float y) {
    ull r; asm("mov.b64 %0, {%1,%2};" : "=l"(r) : "f"(x), "f"(y)); return r;
}
__device__ __forceinline__ void unpack2(ull v, float& x, float& y) {
    asm("mov.b64 {%0,%1}, %2;" : "=f"(x), "=f"(y) : "l"(v));
}
__device__ __forceinline__ ull ffma2(ull a, ull b, ull c) {   // packed f32x2 FMA (sm_100+)
    ull d; asm("fma.rn.f32x2 %0, %1, %2, %3;" : "=l"(d) : "l"(a), "l"(b), "l"(c)); return d;
}

__global__ __launch_bounds__(NT) void gen_cell_kernel(
    const float* __restrict__ qt1,      // [B, M, N, 2]
    const float* __restrict__ ht1,      // [B, N, 2]
    const float* __restrict__ zt,       // [B, N]
    const float* __restrict__ alpha_t,  // [B, N]
    const float* __restrict__ conv_w,   // [2, 2, M+1, 1]
    const float* __restrict__ conv_b,   // [2]
    const float* __restrict__ W_xr, const float* __restrict__ W_hr, const float* __restrict__ b_r,
    const float* __restrict__ W_xu, const float* __restrict__ W_hu, const float* __restrict__ b_u,
    const float* __restrict__ W_xn, const float* __restrict__ W_hn, const float* __restrict__ b_n,
    const float* __restrict__ lin_w,    // [N, 2N]
    const float* __restrict__ lin_b,    // [N]
    const float* __restrict__ W_emb,    // [K, 2]
    float* __restrict__ out)            // st [B,N,2] | qt [B,M,N,2] | ht [B,N,2]
{
    __shared__ __align__(16) ull    s_exy[EMB_SZ];   // interleaved (x,y) emb, zero-padded
    __shared__ __align__(16) float2 s_q[Mn * Nn];    // full q tile, reused for output
    __shared__ float2 s_part[3 * Nn];                // conv partials [group][n]
    __shared__ ull    s_coef2[Nn + 2];               // coef padded to 66 (= 6*11)
    __shared__ __align__(16) float s_ht[2 * Nn];

    const int b    = blockIdx.x;
    const int tid  = threadIdx.x;
    const int lane = tid & 31;
    const int wrp  = tid >> 5;
    const float2* qf = (const float2*)(qt1 + (size_t)b * Mn * Nn * 2);

    // ============ phase 0: emb staging + q tile (reused) + conv partials ============
    {
        const float4* we4 = (const float4*)W_emb;   // 1024 float4 = 2048 (x,y) pairs
        float4 e0 = we4[tid],       e1 = we4[tid + 192], e2 = we4[tid + 384];
        float4 e3 = we4[tid + 576], e4 = we4[tid + 768];
        float4 e5 = make_float4(0.f, 0.f, 0.f, 0.f);
        if (tid < 64) e5 = we4[tid + 960];

        // conv input loads (tap h = g*11+k; tap 32 is the ht1 row)
        const int n = tid & 63;
        const int g = tid >> 6;
        float2 v[11];
        #pragma unroll
        for (int k = 0; k < 11; k++) {
            const int h = g * 11 + k;
            v[k] = (h < 32) ? qf[h * Nn + n] : ((const float2*)ht1)[b * Nn + n];
        }

        // zero pads (emb + coef tail)
        if (tid < PAD) s_exy[tid] = 0ULL;
        if (tid < 64)  s_exy[PAD + Kn + tid] = 0ULL;
        if (tid >= 64 && tid < 66) s_coef2[Nn + (tid - 64)] = 0ULL;

        // staged emb store (interleaved, STS.128)
        float4* exy4 = (float4*)(s_exy + PAD);
        exy4[tid]       = e0;  exy4[tid + 192] = e1;  exy4[tid + 384] = e2;
        exy4[tid + 576] = e3;  exy4[tid + 768] = e4;
        if (tid < 64) exy4[tid + 960] = e5;

        // stash q tile for output assembly
        #pragma unroll
        for (int k = 0; k < 11; k++) {
            const int h = g * 11 + k;
            if (h < 32) s_q[h * Nn + n] = v[k];
        }

        // conv partial sums, dual chains
        float p0a = 0.f, p0b = 0.f, p1a = 0.f, p1b = 0.f;
        #pragma unroll
        for (int k = 0; k < 11; k++) {
            const int h = g * 11 + k;
            const float wa = conv_w[h],      wb = conv_w[33 + h];
            const float wc = conv_w[66 + h], wd = conv_w[99 + h];
            if (k & 1) {
                p0b = fmaf(v[k].x, wa, fmaf(v[k].y, wb, p0b));
                p1b = fmaf(v[k].x, wc, fmaf(v[k].y, wd, p1b));
            } else {
                p0a = fmaf(v[k].x, wa, fmaf(v[k].y, wb, p0a));
                p1a = fmaf(v[k].x, wc, fmaf(v[k].y, wd, p1a));
            }
        }
        s_part[g * Nn + n] = make_float2(p0a + p0b, p1a + p1b);
    }
    __syncthreads();

    // ---- preload lin_w row slices (LDG latency hides under GRU + window preload) ----
    float4 lv[11];
    {
        const float4* lw4 = (const float4*)lin_w;             // [64 rows][32 float4]
        #pragma unroll
        for (int k = 0; k < 11; k++) {
            const int row = wrp * 11 + k;
            lv[k] = (row < Nn) ? lw4[row * 32 + lane] : make_float4(0.f, 0.f, 0.f, 0.f);
        }
    }

    // ---- preload FIR circular window: logical w[i]=emb[p0+i] lives at P[(11-i)%11] ----
    const int p0 = tid * Cn;
    ull acc[Cn], P[Cn];
    #pragma unroll
    for (int i = 0; i < Cn; i++) {
        P[(Cn - i) % Cn] = s_exy[PAD + p0 + i];
        acc[i] = 0ULL;
    }

    // ============ phase 1: GRU per stroke (tid<64; short tail) ============
    if (tid < 64) {
        const int n = tid;
        const float2 hv = ((const float2*)ht1)[b * Nn + n];   // L1 hit
        const float2 pa = s_part[n], pb = s_part[Nn + n], pc = s_part[2 * Nn + n];
        const float h0 = (pa.x + pb.x) + pc.x + conv_b[0];    // ht1 tap already in pc
        const float h1 = (pa.y + pb.y) + pc.y + conv_b[1];

        const float x0 = zt[b * Nn + n];
        const float x1 = alpha_t[b * Nn + n];

        float r0 = sigmoidf_(fmaf(x0, W_xr[0], fmaf(x1, W_xr[2], fmaf(h0, W_hr[0], fmaf(h1, W_hr[2], b_r[0])))));
        float r1 = sigmoidf_(fmaf(x0, W_xr[1], fmaf(x1, W_xr[3], fmaf(h0, W_hr[1], fmaf(h1, W_hr[3], b_r[1])))));
        float u0 = sigmoidf_(fmaf(x0, W_xu[0], fmaf(x1, W_xu[2], fmaf(h0, W_hu[0], fmaf(h1, W_hu[2], b_u[0])))));
        float u1 = sigmoidf_(fmaf(x0, W_xu[1], fmaf(x1, W_xu[3], fmaf(h0, W_hu[1], fmaf(h1, W_hu[3], b_u[1])))));

        const float rh0 = r0 * h0, rh1 = r1 * h1;
        float nt0 = tanhf(fmaf(x0, W_xn[0], fmaf(x1, W_xn[2], fmaf(rh0, W_hn[0], fmaf(rh1, W_hn[2], b_n[0])))));
        float nt1 = tanhf(fmaf(x0, W_xn[1], fmaf(x1, W_xn[3], fmaf(rh0, W_hn[1], fmaf(rh1, W_hn[3], b_n[1])))));

        const float hn0 = u0 * hv.x + (1.0f - u0) * nt0;
        const float hn1 = u1 * hv.y + (1.0f - u1) * nt1;

        s_ht[2 * n + 0] = hn0;
        s_ht[2 * n + 1] = hn1;

        const size_t off_ht = (size_t)Bn * Nn * 2 + (size_t)Bn * Mn * Nn * 2;
        ((float2*)(out + off_ht))[(size_t)b * Nn + n] = make_float2(hn0, hn1);
    }
    __syncthreads();

    // ============ phase 2: coef matvec with preloaded lin_w + shuffle reduce ============
    {
        const float4 ht4 = ((const float4*)s_ht)[lane];
        #pragma unroll
        for (int k = 0; k < 11; k++) {
            const int row = wrp * 11 + k;
            if (row < Nn) {
                const float4 l = lv[k];
                float d = fmaf(l.x, ht4.x, fmaf(l.y, ht4.y, fmaf(l.z, ht4.z, l.w * ht4.w)));
                d += __shfl_xor_sync(0xffffffffu, d, 16);
                d += __shfl_xor_sync(0xffffffffu, d, 8);
                d += __shfl_xor_sync(0xffffffffu, d, 4);
                d += __shfl_xor_sync(0xffffffffu, d, 2);
                d += __shfl_xor_sync(0xffffffffu, d, 1);
                if (lane == 0) {
                    const float c = (d + lin_b[row]) * alpha_t[b * Nn + row];
                    s_coef2[row] = pack2(c, c);
                }
            }
        }
    }
    __syncthreads();

    // ============ phase 3: FIR, circular buffer, 6 rolled blocks x 11 unrolled ============
    // Invariant at iteration n: logical w[i] = emb[p0+i-n] lives at P[(n-i) mod 11].
    // Per sub-iter j (n = nb+j): consume dying slot P[(j+1)%11] (i=10) first, reload it,
    // then remaining FMAs i=9..0 — the reload's next consumer is ~20 instrs away.
    #pragma unroll 1
    for (int blk = 0; blk < 6; blk++) {           // rolled: inner body ~2.3KB, L0-resident
        const int nb = blk * Cn;
        #pragma unroll
        for (int j = 0; j < Cn; j++) {
            const ull c2 = s_coef2[nb + j];       // broadcast (rows 64,65 are zero pads)
            acc[10] = ffma2(c2, P[(j + 1) % Cn], acc[10]);
            P[(j + 1) % Cn] = s_exy[PAD + p0 - (nb + j) - 1];   // min idx = PAD-66 = 6
            #pragma unroll
            for (int i = 9; i >= 0; i--)
                acc[i] = ffma2(c2, P[(j - i + 22) % Cn], acc[i]);
        }
    }

    // ============ output assembly (q operands from shared) ============
    float2* st_out = (float2*)out + (size_t)b * Nn;
    float2* qt_out = (float2*)(out + (size_t)Bn * Nn * 2) + (size_t)b * Mn * Nn;
    #pragma unroll
    for (int i = 0; i < Cn; i++) {
        const int p = p0 + i;
        float fx, fy; unpack2(acc[i], fx, fy);
        float2 qv = make_float2(0.0f, 0.0f);
        if (p < Mn * Nn) qv = s_q[p];              // q_shift[j] = q_flat[j+N] = q_flat[p]
        float2 r = make_float2(qv.x + fx, qv.y + fy);
        if (p < Nn) st_out[p] = r;                 // st = q_row0 + f[:N]
        else        qt_out[p - Nn] = r;            // qt = q_shift + tail
    }
}

extern "C" void kernel_launch(void* const* d_in, const int* in_sizes, int n_in,
                              void* d_out, int out_size) {
    const float* qt1     = (const float*)d_in[0];
    const float* ht1     = (const float*)d_in[1];
    const float* zt      = (const float*)d_in[2];
    const float* alpha_t = (const float*)d_in[3];
    const float* conv_w  = (const float*)d_in[4];
    const float* conv_b  = (const float*)d_in[5];
    const float* W_xr    = (const float*)d_in[6];
    const float* W_hr    = (const float*)d_in[7];
    const float* b_r     = (const float*)d_in[8];
    const float* W_xu    = (const float*)d_in[9];
    const float* W_hu    = (const float*)d_in[10];
    const float* b_u     = (const float*)d_in[11];
    const float* W_xn    = (const float*)d_in[12];
    const float* W_hn    = (const float*)d_in[13];
    const float* b_n     = (const float*)d_in[14];
    const float* lin_w   = (const float*)d_in[15];
    const float* lin_b   = (const float*)d_in[16];
    const float* W_emb   = (const float*)d_in[17];

    gen_cell_kernel<<<Bn, NT>>>(qt1, ht1, zt, alpha_t, conv_w, conv_b,
                                W_xr, W_hr, b_r, W_xu, W_hu, b_u,
                                W_xn, W_hn, b_n, lin_w, lin_b, W_emb,
                                (float*)d_out);
}